// round 6
// baseline (speedup 1.0000x reference)
#include <cuda_runtime.h>
#include <cstdint>

// Problem constants
#define T_DIM 2048
#define B_DIM 4
#define C_DIM 1024
#define H_DIM 16
#define K_TAPS 15
#define M_DIM (T_DIM * B_DIM)     // 8192 rows (t*B + b)
#define N_DIM (H_DIM * K_TAPS)    // 240 logits per row
#define KD    C_DIM               // 1024 reduction dim

// Scratch: softmaxed dynamic weights (T*B, 240) fp32; pre-rounded tf32 Wlin
__device__ float    g_w[M_DIM * N_DIM];
__device__ uint32_t g_bw[N_DIM * KD];

__device__ __forceinline__ uint32_t f2tf(float f) {
    uint32_t u;
    asm("cvt.rna.tf32.f32 %0, %1;" : "=r"(u) : "f"(f));
    return u;
}

// ---------------- Prologue: Wlin -> tf32(rna) bits, once ----------------
extern "C" __global__ void __launch_bounds__(256)
cvt_b_kernel(const float* __restrict__ W) {
    int base = blockIdx.x * 256 + threadIdx.x;
    #pragma unroll
    for (int k = 0; k < 4; k++) {
        int i = base + k * 15360;
        float4 v = ((const float4*)W)[i];
        uint4 o;
        o.x = f2tf(v.x); o.y = f2tf(v.y); o.z = f2tf(v.z); o.w = f2tf(v.w);
        ((uint4*)g_bw)[i] = o;
    }
}

// ======= GEMM (tf32 mma.sync, split-K, 3-stage cp.async) + softmax =======
// Block: BM=64 rows, N=240 exact, 384 threads = 12 warps:
//   2 k-groups (512 k each) x 6 N-groups (40 cols each).
// Warp tile m64 x n40: 20 MMAs/kk-step, acc 80 regs.
// Per k-group: 3 stages of BK=16, depth-2 prefetch, 1 barrier per tile.
#define NTHR   384
#define GSIZE  192                // threads per k-group
#define BM     64
#define BK     16
#define KHALF  (KD / 2)           // 512 per k-group
#define NT_KG  (KHALF / BK)       // 32 tiles per k-group
#define AST    20                 // padded strides (words)
#define BST    20
#define A_STG  (BM * AST)         // 1280 words
#define B_STG  (N_DIM * BST)      // 4800 words
#define STG_W  (A_STG + B_STG)    // 6080 words = 24320 B
#define GEMM_SMEM (6 * STG_W * 4) // 145920 B (3 stages x 2 k-groups)
#define CST    242
#define NTW    5                  // n8-tiles per warp (40 cols)

extern "C" __global__ void __launch_bounds__(NTHR, 1)
gemm_softmax_kernel(const float* __restrict__ x) {
    extern __shared__ uint32_t sm[];
    const int tid  = threadIdx.x;
    const int wid  = tid >> 5;
    const int lane = tid & 31;
    const int m0   = blockIdx.x * BM;

    const int kg   = (wid >= 6) ? 1 : 0;   // k-split group
    const int ng   = wid - kg * 6;         // N-group: cols [ng*40, ng*40+40)
    const int gtid = tid - kg * GSIZE;     // thread id within k-group
    const int lg   = lane >> 2;
    const int lk   = lane & 3;
    const int kofs = kg * KHALF;

    // Issue cp.async loads of one BK=16 tile into stage st (group-collective)
    auto issue_tile = [&](int kb, int st) {
        uint32_t* As = sm + st * STG_W;
        uint32_t* Bs = As + A_STG;
        // A: 64 rows x 16 k = 256 float4
        #pragma unroll
        for (int i = 0; i < 2; i++) {
            int idx = i * GSIZE + gtid;
            if (idx < 256) {
                int m = idx >> 2, kq = idx & 3;
                const float* src = x + (size_t)(m0 + m) * KD + kb + kq * 4;
                uint32_t dst = (uint32_t)__cvta_generic_to_shared(As + m * AST + kq * 4);
                asm volatile("cp.async.cg.shared.global [%0], [%1], 16;\n"
                             :: "r"(dst), "l"(src));
            }
        }
        // B: 240 rows x 16 k = 960 float4 = 5 per thread exactly
        #pragma unroll
        for (int i = 0; i < 5; i++) {
            int idx = i * GSIZE + gtid;
            int n = idx >> 2, kq = idx & 3;
            const uint32_t* src = g_bw + (size_t)n * KD + kb + kq * 4;
            uint32_t dst = (uint32_t)__cvta_generic_to_shared(Bs + n * BST + kq * 4);
            asm volatile("cp.async.cg.shared.global [%0], [%1], 16;\n"
                         :: "r"(dst), "l"(src));
        }
        asm volatile("cp.async.commit_group;\n");
    };

    float acc[4][NTW][4];   // [m-tile][n-tile][frag]
    #pragma unroll
    for (int a = 0; a < 4; a++)
        #pragma unroll
        for (int b = 0; b < NTW; b++)
            #pragma unroll
            for (int c = 0; c < 4; c++) acc[a][b][c] = 0.f;

    // Prologue: prefetch tiles 0 and 1 of this k-group
    issue_tile(kofs, kg * 3);
    issue_tile(kofs + BK, kg * 3 + 1);

    const int baridx = 1 + kg;   // named barrier per k-group (192 threads)

    for (int j = 0; j < NT_KG; j++) {
        if (j == NT_KG - 1) asm volatile("cp.async.wait_group 0;\n");
        else                asm volatile("cp.async.wait_group 1;\n");
        asm volatile("bar.sync %0, %1;" :: "r"(baridx), "n"(GSIZE) : "memory");

        // Issue tile j+2 BEFORE compute (stage (j+2)%3 was freed at iter j-1)
        if (j + 2 < NT_KG) issue_tile(kofs + (j + 2) * BK, kg * 3 + (j + 2) % 3);

        const uint32_t* As = sm + (kg * 3 + j % 3) * STG_W;
        const uint32_t* Bs = As + A_STG;

        #pragma unroll
        for (int kk = 0; kk < BK; kk += 8) {
            uint32_t a0[4], a1[4], a2[4], a3[4];
            #pragma unroll
            for (int mt = 0; mt < 4; mt++) {
                a0[mt] = As[(mt * 16     + lg) * AST + kk     + lk];
                a1[mt] = As[(mt * 16 + 8 + lg) * AST + kk     + lk];
                a2[mt] = As[(mt * 16     + lg) * AST + kk + 4 + lk];
                a3[mt] = As[(mt * 16 + 8 + lg) * AST + kk + 4 + lk];
            }
            #pragma unroll
            for (int nt = 0; nt < NTW; nt++) {
                const int col = ng * 40 + nt * 8;
                uint32_t b0 = Bs[(col + lg) * BST + kk     + lk];
                uint32_t b1 = Bs[(col + lg) * BST + kk + 4 + lk];
                #pragma unroll
                for (int mt = 0; mt < 4; mt++) {
                    asm volatile(
                        "mma.sync.aligned.m16n8k8.row.col.f32.tf32.tf32.f32 "
                        "{%0,%1,%2,%3}, {%4,%5,%6,%7}, {%8,%9}, {%0,%1,%2,%3};\n"
                        : "+f"(acc[mt][nt][0]), "+f"(acc[mt][nt][1]),
                          "+f"(acc[mt][nt][2]), "+f"(acc[mt][nt][3])
                        : "r"(a0[mt]), "r"(a1[mt]), "r"(a2[mt]), "r"(a3[mt]),
                          "r"(b0), "r"(b1));
                }
            }
        }
    }

    // ---- Split-K reduction + softmax (block-wide) ----
    __syncthreads();                 // all stages dead; reuse smem as Cs
    float* Cs = (float*)sm;          // [64][242]

    if (kg == 1) {
        #pragma unroll
        for (int mt = 0; mt < 4; mt++)
            #pragma unroll
            for (int nt = 0; nt < NTW; nt++) {
                int col = ng * 40 + nt * 8 + 2 * lk;
                int row = mt * 16 + lg;
                Cs[row * CST + col    ]       = acc[mt][nt][0];
                Cs[row * CST + col + 1]       = acc[mt][nt][1];
                Cs[(row + 8) * CST + col    ] = acc[mt][nt][2];
                Cs[(row + 8) * CST + col + 1] = acc[mt][nt][3];
            }
    }
    __syncthreads();
    if (kg == 0) {
        #pragma unroll
        for (int mt = 0; mt < 4; mt++)
            #pragma unroll
            for (int nt = 0; nt < NTW; nt++) {
                int col = ng * 40 + nt * 8 + 2 * lk;
                int row = mt * 16 + lg;
                Cs[row * CST + col    ]       += acc[mt][nt][0];
                Cs[row * CST + col + 1]       += acc[mt][nt][1];
                Cs[(row + 8) * CST + col    ] += acc[mt][nt][2];
                Cs[(row + 8) * CST + col + 1] += acc[mt][nt][3];
            }
    }
    __syncthreads();

    // Softmax over K=15 per (row, head): 64*16 = 1024 tasks
    #pragma unroll
    for (int it = 0; it < 3; it++) {
        int task = it * NTHR + tid;
        if (task < BM * H_DIM) {
            int row = task >> 4, h = task & 15;
            const float* p = Cs + row * CST + h * K_TAPS;
            float mx = p[0];
            #pragma unroll
            for (int k = 1; k < K_TAPS; k++) mx = fmaxf(mx, p[k]);
            float e[K_TAPS];
            float s = 0.f;
            #pragma unroll
            for (int k = 0; k < K_TAPS; k++) { e[k] = __expf(p[k] - mx); s += e[k]; }
            float r = 1.0f / s;
            float* o = g_w + (size_t)(m0 + row) * N_DIM + h * K_TAPS;
            #pragma unroll
            for (int k = 0; k < K_TAPS; k++) o[k] = e[k] * r;
        }
    }
}

// ---------------- Dynamic depthwise conv (causal, K=15) ----------------
// out[t,b,c] = sum_k w[t,b,h(c),k] * x[t+k-14, b, c]
#define TT 32   // time steps per block

extern "C" __global__ void __launch_bounds__(256, 2)
dynconv_kernel(const float* __restrict__ x, float* __restrict__ out) {
    __shared__ float ws[TT * N_DIM];   // 30 KB

    const int tid = threadIdx.x;
    const int t0  = blockIdx.x * TT;
    const int b   = blockIdx.y;

    const int c4 = tid;           // float4 channel group (c = 4*tid)
    const int h  = tid >> 4;      // head

    const float4* x4 = (const float4*)x;
    float4*       o4 = (float4*)out;

    // Register window loads first: 15 independent LDGs in flight
    float4 win[K_TAPS];
    #pragma unroll
    for (int i = 0; i < K_TAPS; i++) {
        int t = t0 - 14 + i;
        win[i] = (t < 0) ? make_float4(0.f, 0.f, 0.f, 0.f)
                         : x4[(size_t)(t * B_DIM + b) * (C_DIM / 4) + c4];
    }

    const float4* gw4 = (const float4*)g_w;
    #pragma unroll
    for (int it = 0; it < 8; it++) {
        int idx = it * 256 + tid;
        if (idx < TT * (N_DIM / 4)) {
            int tt = idx / (N_DIM / 4), q = idx % (N_DIM / 4);
            ((float4*)ws)[tt * (N_DIM / 4) + q] =
                gw4[(size_t)((t0 + tt) * B_DIM + b) * (N_DIM / 4) + q];
        }
    }
    __syncthreads();

    #pragma unroll
    for (int tt = 0; tt < TT; tt++) {
        float4 nxt;
        if (tt + 1 < TT)
            nxt = x4[(size_t)((t0 + tt + 1) * B_DIM + b) * (C_DIM / 4) + c4];

        const float* wr = ws + tt * N_DIM + h * K_TAPS;
        float4 a = make_float4(0.f, 0.f, 0.f, 0.f);
        #pragma unroll
        for (int k = 0; k < K_TAPS; k++) {
            const float w = wr[k];
            const float4 xv = win[(tt + k) % K_TAPS];
            a.x += w * xv.x; a.y += w * xv.y;
            a.z += w * xv.z; a.w += w * xv.w;
        }
        o4[(size_t)((t0 + tt) * B_DIM + b) * (C_DIM / 4) + c4] = a;
        if (tt + 1 < TT) win[tt % K_TAPS] = nxt;
    }
}

extern "C" void kernel_launch(void* const* d_in, const int* in_sizes, int n_in,
                              void* d_out, int out_size) {
    const float* x    = (const float*)d_in[0];   // (T, B, C) f32
    const float* Wlin = (const float*)d_in[1];   // (240, 1024) f32
    float* out = (float*)d_out;                  // (T, B, C) f32

    cudaFuncSetAttribute(gemm_softmax_kernel,
                         cudaFuncAttributeMaxDynamicSharedMemorySize,
                         GEMM_SMEM);

    cvt_b_kernel<<<60, 256>>>(Wlin);
    gemm_softmax_kernel<<<M_DIM / BM, NTHR, GEMM_SMEM>>>(x);
    dynconv_kernel<<<dim3(T_DIM / TT, B_DIM), 256>>>(x, out);
}

// round 7
// speedup vs baseline: 1.4617x; 1.4617x over previous
#include <cuda_runtime.h>
#include <cuda_fp16.h>
#include <cstdint>

// Problem constants
#define T_DIM 2048
#define B_DIM 4
#define C_DIM 1024
#define H_DIM 16
#define K_TAPS 15
#define M_DIM (T_DIM * B_DIM)     // 8192 rows (t*B + b)
#define N_DIM (H_DIM * K_TAPS)    // 240 logits per row
#define KD    C_DIM               // 1024 reduction dim

// Scratch: softmaxed dynamic weights (T*B, 240) fp32; fp16 Wlin
__device__ float  g_w[M_DIM * N_DIM];
__device__ __half g_wh[N_DIM * KD];

// ---------------- Prologue: Wlin -> fp16, once ----------------
extern "C" __global__ void __launch_bounds__(256)
cvt_b_kernel(const float* __restrict__ W) {
    int base = blockIdx.x * 256 + threadIdx.x;
    #pragma unroll
    for (int k = 0; k < 4; k++) {
        int i = base + k * 15360;               // 61440 float4 total
        float4 v = ((const float4*)W)[i];
        __half2 h0 = __floats2half2_rn(v.x, v.y);
        __half2 h1 = __floats2half2_rn(v.z, v.w);
        uint2 o;
        o.x = *(uint32_t*)&h0;
        o.y = *(uint32_t*)&h1;
        ((uint2*)g_wh)[i] = o;
    }
}

// ===== GEMM (fp16 mma m16n8k16 + ldmatrix, split-K 2) + fused softmax =====
// Block: BM=64 rows, BN padded 256, 512 threads = 16 warps:
//   2 k-groups (512 k each) x 8 N-groups (32 cols each). Warp tile m64 x n32.
// B: cp.async fp16 (pre-converted), 2 stages per k-group, BK=64.
// A: LDG float4 -> cvt half -> STS, one tile ahead (register staged).
#define NTHR   512
#define GSIZE  256
#define BM     64
#define BK     64
#define KHALF  (KD / 2)           // 512 per k-group
#define NT_KG  (KHALF / BK)       // 8 tiles per k-group
#define ASTH   72                 // A row stride in halves (144B; 9x16B, conflict-free)
#define BSTH   72
#define A_STG_H (BM * ASTH)       // 4608 halves
#define B_STG_H (256 * BSTH)      // 18432 halves
#define STG_H   (A_STG_H + B_STG_H)
#define GEMM_SMEM (4 * STG_H * 2) // 184320 B (2 stages x 2 k-groups)
#define CST    242

__device__ __forceinline__ uint32_t s2u(const void* p) {
    return (uint32_t)__cvta_generic_to_shared(p);
}

extern "C" __global__ void __launch_bounds__(NTHR, 1)
gemm_softmax_kernel(const float* __restrict__ x) {
    extern __shared__ __half sh[];
    const int tid  = threadIdx.x;
    const int wid  = tid >> 5;
    const int lane = tid & 31;
    const int m0   = blockIdx.x * BM;

    const int kg   = wid >> 3;          // k-split group 0/1
    const int ng   = wid & 7;           // N-group: cols [ng*32, ng*32+32)
    const int gtid = tid & 255;         // thread id within k-group
    const int lg   = lane >> 2;
    const int lk   = lane & 3;
    const int kofs = kg * KHALF;

    // --- B tile via cp.async (fp16): 256 rows x 64 k, rows >=240 zero-fill
    auto issue_b = [&](int kb, int st) {
        __half* Bs = sh + st * STG_H + A_STG_H;
        #pragma unroll
        for (int i = 0; i < 8; i++) {
            int idx = i * GSIZE + gtid;          // 0..2047 16B-chunks
            int n = idx >> 3, kq = idx & 7;
            int nn = (n < N_DIM) ? n : 0;
            unsigned bytes = (n < N_DIM) ? 16u : 0u;
            const __half* src = g_wh + (size_t)nn * KD + kb + kq * 8;
            uint32_t dst = s2u(Bs + n * BSTH + kq * 8);
            asm volatile("cp.async.cg.shared.global [%0], [%1], 16, %2;\n"
                         :: "r"(dst), "l"(src), "r"(bytes));
        }
        asm volatile("cp.async.commit_group;\n");
    };

    // --- A tile: LDG float4 -> half2x2 regs (4 chunks/thread)
    uint2 areg[4];
    auto ldg_a = [&](int kb) {
        #pragma unroll
        for (int i = 0; i < 4; i++) {
            int idx = i * GSIZE + gtid;          // 0..1023 float4 chunks
            int m = idx >> 4, kq = idx & 15;
            float4 v = *(const float4*)(x + (size_t)(m0 + m) * KD + kb + kq * 4);
            __half2 h0 = __floats2half2_rn(v.x, v.y);
            __half2 h1 = __floats2half2_rn(v.z, v.w);
            areg[i].x = *(uint32_t*)&h0;
            areg[i].y = *(uint32_t*)&h1;
        }
    };
    auto sts_a = [&](int st) {
        __half* As = sh + st * STG_H;
        #pragma unroll
        for (int i = 0; i < 4; i++) {
            int idx = i * GSIZE + gtid;
            int m = idx >> 4, kq = idx & 15;
            *(uint2*)(As + m * ASTH + kq * 4) = areg[i];
        }
    };

    float acc[4][4][4];   // [m-tile][n-tile][frag]
    #pragma unroll
    for (int a = 0; a < 4; a++)
        #pragma unroll
        for (int b = 0; b < 4; b++)
            #pragma unroll
            for (int c = 0; c < 4; c++) acc[a][b][c] = 0.f;

    // Prologue
    ldg_a(kofs);                 // A(0)
    issue_b(kofs, kg * 2);       // B(0)
    issue_b(kofs + BK, kg * 2 + 1);   // B(1)
    sts_a(kg * 2);               // A(0) -> stage0 (reg dep stalls on LDG)
    ldg_a(kofs + BK);            // A(1)

    const int baridx = 1 + kg;   // named barrier per k-group (256 threads)

    for (int j = 0; j < NT_KG; j++) {
        const int st = kg * 2 + (j & 1);
        if (j == NT_KG - 1) asm volatile("cp.async.wait_group 0;\n");
        else                asm volatile("cp.async.wait_group 1;\n");
        asm volatile("bar.sync %0, %1;" :: "r"(baridx), "n"(GSIZE) : "memory");

        // Stage A(j+1) into the other buffer (freed: compute(j-1) done by all)
        if (j + 1 < NT_KG) sts_a(kg * 2 + ((j + 1) & 1));
        if (j + 2 < NT_KG) ldg_a(kofs + (j + 2) * BK);

        const __half* As = sh + st * STG_H;
        const __half* Bs = As + A_STG_H;

        #pragma unroll
        for (int kk = 0; kk < BK; kk += 16) {
            // A frags: 4x ldmatrix.x4 (m16k16 each)
            uint32_t a[4][4];
            #pragma unroll
            for (int mt = 0; mt < 4; mt++) {
                uint32_t ad = s2u(As + (mt * 16 + (lane & 15)) * ASTH
                                     + kk + (lane >> 4) * 8);
                asm volatile(
                    "ldmatrix.sync.aligned.m8n8.x4.shared.b16 {%0,%1,%2,%3}, [%4];"
                    : "=r"(a[mt][0]), "=r"(a[mt][1]), "=r"(a[mt][2]), "=r"(a[mt][3])
                    : "r"(ad));
            }
            // B frags: 2x ldmatrix.x4, each covers two n8 tiles (k-lo/k-hi)
            uint32_t bfr[4][2];
            #pragma unroll
            for (int nh = 0; nh < 2; nh++) {
                int col = ng * 32 + nh * 16;
                uint32_t bd = s2u(Bs + (col + (lane & 7) + ((lane >> 4) & 1) * 8) * BSTH
                                     + kk + ((lane >> 3) & 1) * 8);
                uint32_t r0, r1, r2, r3;
                asm volatile(
                    "ldmatrix.sync.aligned.m8n8.x4.shared.b16 {%0,%1,%2,%3}, [%4];"
                    : "=r"(r0), "=r"(r1), "=r"(r2), "=r"(r3) : "r"(bd));
                bfr[nh * 2][0] = r0;  bfr[nh * 2][1] = r1;      // n8 tile @ col
                bfr[nh * 2 + 1][0] = r2; bfr[nh * 2 + 1][1] = r3; // @ col+8
            }
            #pragma unroll
            for (int nt = 0; nt < 4; nt++)
                #pragma unroll
                for (int mt = 0; mt < 4; mt++) {
                    asm volatile(
                        "mma.sync.aligned.m16n8k16.row.col.f32.f16.f16.f32 "
                        "{%0,%1,%2,%3}, {%4,%5,%6,%7}, {%8,%9}, {%0,%1,%2,%3};\n"
                        : "+f"(acc[mt][nt][0]), "+f"(acc[mt][nt][1]),
                          "+f"(acc[mt][nt][2]), "+f"(acc[mt][nt][3])
                        : "r"(a[mt][0]), "r"(a[mt][1]), "r"(a[mt][2]), "r"(a[mt][3]),
                          "r"(bfr[nt][0]), "r"(bfr[nt][1]));
                }
        }
        asm volatile("bar.sync %0, %1;" :: "r"(baridx), "n"(GSIZE) : "memory");
        if (j + 2 < NT_KG) issue_b(kofs + (j + 2) * BK, st);
    }

    // ---- Split-K reduction + softmax (block-wide) ----
    __syncthreads();                 // all stages dead; reuse smem as Cs
    float* Cs = (float*)sh;          // [64][242]

    if (kg == 1) {
        #pragma unroll
        for (int mt = 0; mt < 4; mt++)
            #pragma unroll
            for (int nt = 0; nt < 4; nt++) {
                int col = ng * 32 + nt * 8 + 2 * lk;
                if (col < N_DIM) {
                    int row = mt * 16 + lg;
                    Cs[row * CST + col    ]       = acc[mt][nt][0];
                    Cs[row * CST + col + 1]       = acc[mt][nt][1];
                    Cs[(row + 8) * CST + col    ] = acc[mt][nt][2];
                    Cs[(row + 8) * CST + col + 1] = acc[mt][nt][3];
                }
            }
    }
    __syncthreads();
    if (kg == 0) {
        #pragma unroll
        for (int mt = 0; mt < 4; mt++)
            #pragma unroll
            for (int nt = 0; nt < 4; nt++) {
                int col = ng * 32 + nt * 8 + 2 * lk;
                if (col < N_DIM) {
                    int row = mt * 16 + lg;
                    Cs[row * CST + col    ]       += acc[mt][nt][0];
                    Cs[row * CST + col + 1]       += acc[mt][nt][1];
                    Cs[(row + 8) * CST + col    ] += acc[mt][nt][2];
                    Cs[(row + 8) * CST + col + 1] += acc[mt][nt][3];
                }
            }
    }
    __syncthreads();

    // Softmax over K=15 per (row, head): 64*16 = 1024 tasks
    #pragma unroll
    for (int it = 0; it < 2; it++) {
        int task = it * NTHR + tid;
        int row = task >> 4, h = task & 15;
        const float* p = Cs + row * CST + h * K_TAPS;
        float mx = p[0];
        #pragma unroll
        for (int k = 1; k < K_TAPS; k++) mx = fmaxf(mx, p[k]);
        float e[K_TAPS];
        float s = 0.f;
        #pragma unroll
        for (int k = 0; k < K_TAPS; k++) { e[k] = __expf(p[k] - mx); s += e[k]; }
        float r = 1.0f / s;
        float* o = g_w + (size_t)(m0 + row) * N_DIM + h * K_TAPS;
        #pragma unroll
        for (int k = 0; k < K_TAPS; k++) o[k] = e[k] * r;
    }
}

// ---------------- Dynamic depthwise conv (causal, K=15) ----------------
// out[t,b,c] = sum_k w[t,b,h(c),k] * x[t+k-14, b, c]
#define TT 32   // time steps per block

extern "C" __global__ void __launch_bounds__(256, 2)
dynconv_kernel(const float* __restrict__ x, float* __restrict__ out) {
    __shared__ float ws[TT * N_DIM];   // 30 KB

    const int tid = threadIdx.x;
    const int t0  = blockIdx.x * TT;
    const int b   = blockIdx.y;

    const int c4 = tid;           // float4 channel group (c = 4*tid)
    const int h  = tid >> 4;      // head

    const float4* x4 = (const float4*)x;
    float4*       o4 = (float4*)out;

    // Register window loads first: 15 independent LDGs in flight
    float4 win[K_TAPS];
    #pragma unroll
    for (int i = 0; i < K_TAPS; i++) {
        int t = t0 - 14 + i;
        win[i] = (t < 0) ? make_float4(0.f, 0.f, 0.f, 0.f)
                         : x4[(size_t)(t * B_DIM + b) * (C_DIM / 4) + c4];
    }

    const float4* gw4 = (const float4*)g_w;
    #pragma unroll
    for (int it = 0; it < 8; it++) {
        int idx = it * 256 + tid;
        if (idx < TT * (N_DIM / 4)) {
            int tt = idx / (N_DIM / 4), q = idx % (N_DIM / 4);
            ((float4*)ws)[tt * (N_DIM / 4) + q] =
                gw4[(size_t)((t0 + tt) * B_DIM + b) * (N_DIM / 4) + q];
        }
    }
    __syncthreads();

    #pragma unroll
    for (int tt = 0; tt < TT; tt++) {
        float4 nxt;
        if (tt + 1 < TT)
            nxt = x4[(size_t)((t0 + tt + 1) * B_DIM + b) * (C_DIM / 4) + c4];

        const float* wr = ws + tt * N_DIM + h * K_TAPS;
        float4 a = make_float4(0.f, 0.f, 0.f, 0.f);
        #pragma unroll
        for (int k = 0; k < K_TAPS; k++) {
            const float w = wr[k];
            const float4 xv = win[(tt + k) % K_TAPS];
            a.x += w * xv.x; a.y += w * xv.y;
            a.z += w * xv.z; a.w += w * xv.w;
        }
        o4[(size_t)((t0 + tt) * B_DIM + b) * (C_DIM / 4) + c4] = a;
        if (tt + 1 < TT) win[tt % K_TAPS] = nxt;
    }
}

extern "C" void kernel_launch(void* const* d_in, const int* in_sizes, int n_in,
                              void* d_out, int out_size) {
    const float* x    = (const float*)d_in[0];   // (T, B, C) f32
    const float* Wlin = (const float*)d_in[1];   // (240, 1024) f32
    float* out = (float*)d_out;                  // (T, B, C) f32

    cudaFuncSetAttribute(gemm_softmax_kernel,
                         cudaFuncAttributeMaxDynamicSharedMemorySize,
                         GEMM_SMEM);

    cvt_b_kernel<<<60, 256>>>(Wlin);
    gemm_softmax_kernel<<<M_DIM / BM, NTHR, GEMM_SMEM>>>(x);
    dynconv_kernel<<<dim3(T_DIM / TT, B_DIM), 256>>>(x, out);
}

// round 8
// speedup vs baseline: 1.7669x; 1.2088x over previous
#include <cuda_runtime.h>
#include <cuda_fp16.h>
#include <cstdint>

// Problem constants
#define T_DIM 2048
#define B_DIM 4
#define C_DIM 1024
#define H_DIM 16
#define K_TAPS 15
#define M_DIM (T_DIM * B_DIM)     // 8192 rows (t*B + b)
#define N_DIM (H_DIM * K_TAPS)    // 240 logits per row
#define NPAD  256                 // padded: 16 taps per head
#define KD    C_DIM               // 1024 reduction dim

// Scratch: softmaxed dynamic weights (T*B, 256 padded) fp32; fp16 Wlin
__device__ float  g_w[M_DIM * NPAD];
__device__ __half g_wh[N_DIM * KD];

// ---------------- Prologue: Wlin -> fp16, once ----------------
extern "C" __global__ void __launch_bounds__(256)
cvt_b_kernel(const float* __restrict__ W) {
    int base = blockIdx.x * 256 + threadIdx.x;
    #pragma unroll
    for (int k = 0; k < 4; k++) {
        int i = base + k * 15360;               // 61440 float4 total
        float4 v = ((const float4*)W)[i];
        __half2 h0 = __floats2half2_rn(v.x, v.y);
        __half2 h1 = __floats2half2_rn(v.z, v.w);
        uint2 o;
        o.x = *(uint32_t*)&h0;
        o.y = *(uint32_t*)&h1;
        ((uint2*)g_wh)[i] = o;
    }
}

// ===== GEMM (fp16 mma m16n8k16 + ldmatrix, split-K 2) + fused softmax =====
#define NTHR   512
#define GSIZE  256
#define BM     64
#define BK     64
#define KHALF  (KD / 2)           // 512 per k-group
#define NT_KG  (KHALF / BK)       // 8 tiles per k-group
#define ASTH   72                 // A row stride in halves
#define BSTH   72
#define A_STG_H (BM * ASTH)       // 4608 halves
#define B_STG_H (256 * BSTH)      // 18432 halves
#define STG_H   (A_STG_H + B_STG_H)
#define GEMM_SMEM (4 * STG_H * 2) // 184320 B (2 stages x 2 k-groups)
#define CST    242

__device__ __forceinline__ uint32_t s2u(const void* p) {
    return (uint32_t)__cvta_generic_to_shared(p);
}

extern "C" __global__ void __launch_bounds__(NTHR, 1)
gemm_softmax_kernel(const float* __restrict__ x) {
    extern __shared__ __half sh[];
    const int tid  = threadIdx.x;
    const int wid  = tid >> 5;
    const int lane = tid & 31;
    const int m0   = blockIdx.x * BM;

    const int kg   = wid >> 3;          // k-split group 0/1
    const int ng   = wid & 7;           // N-group: cols [ng*32, ng*32+32)
    const int gtid = tid & 255;         // thread id within k-group
    const int lg   = lane >> 2;
    const int lk   = lane & 3;
    const int kofs = kg * KHALF;

    auto issue_b = [&](int kb, int st) {
        __half* Bs = sh + st * STG_H + A_STG_H;
        #pragma unroll
        for (int i = 0; i < 8; i++) {
            int idx = i * GSIZE + gtid;          // 0..2047 16B-chunks
            int n = idx >> 3, kq = idx & 7;
            int nn = (n < N_DIM) ? n : 0;
            unsigned bytes = (n < N_DIM) ? 16u : 0u;
            const __half* src = g_wh + (size_t)nn * KD + kb + kq * 8;
            uint32_t dst = s2u(Bs + n * BSTH + kq * 8);
            asm volatile("cp.async.cg.shared.global [%0], [%1], 16, %2;\n"
                         :: "r"(dst), "l"(src), "r"(bytes));
        }
        asm volatile("cp.async.commit_group;\n");
    };

    uint2 areg[4];
    auto ldg_a = [&](int kb) {
        #pragma unroll
        for (int i = 0; i < 4; i++) {
            int idx = i * GSIZE + gtid;          // 0..1023 float4 chunks
            int m = idx >> 4, kq = idx & 15;
            float4 v = *(const float4*)(x + (size_t)(m0 + m) * KD + kb + kq * 4);
            __half2 h0 = __floats2half2_rn(v.x, v.y);
            __half2 h1 = __floats2half2_rn(v.z, v.w);
            areg[i].x = *(uint32_t*)&h0;
            areg[i].y = *(uint32_t*)&h1;
        }
    };
    auto sts_a = [&](int st) {
        __half* As = sh + st * STG_H;
        #pragma unroll
        for (int i = 0; i < 4; i++) {
            int idx = i * GSIZE + gtid;
            int m = idx >> 4, kq = idx & 15;
            *(uint2*)(As + m * ASTH + kq * 4) = areg[i];
        }
    };

    float acc[4][4][4];   // [m-tile][n-tile][frag]
    #pragma unroll
    for (int a = 0; a < 4; a++)
        #pragma unroll
        for (int b = 0; b < 4; b++)
            #pragma unroll
            for (int c = 0; c < 4; c++) acc[a][b][c] = 0.f;

    // Prologue
    ldg_a(kofs);
    issue_b(kofs, kg * 2);
    issue_b(kofs + BK, kg * 2 + 1);
    sts_a(kg * 2);
    ldg_a(kofs + BK);

    const int baridx = 1 + kg;

    for (int j = 0; j < NT_KG; j++) {
        const int st = kg * 2 + (j & 1);
        if (j == NT_KG - 1) asm volatile("cp.async.wait_group 0;\n");
        else                asm volatile("cp.async.wait_group 1;\n");
        asm volatile("bar.sync %0, %1;" :: "r"(baridx), "n"(GSIZE) : "memory");

        if (j + 1 < NT_KG) sts_a(kg * 2 + ((j + 1) & 1));
        if (j + 2 < NT_KG) ldg_a(kofs + (j + 2) * BK);

        const __half* As = sh + st * STG_H;
        const __half* Bs = As + A_STG_H;

        #pragma unroll
        for (int kk = 0; kk < BK; kk += 16) {
            uint32_t a[4][4];
            #pragma unroll
            for (int mt = 0; mt < 4; mt++) {
                uint32_t ad = s2u(As + (mt * 16 + (lane & 15)) * ASTH
                                     + kk + (lane >> 4) * 8);
                asm volatile(
                    "ldmatrix.sync.aligned.m8n8.x4.shared.b16 {%0,%1,%2,%3}, [%4];"
                    : "=r"(a[mt][0]), "=r"(a[mt][1]), "=r"(a[mt][2]), "=r"(a[mt][3])
                    : "r"(ad));
            }
            uint32_t bfr[4][2];
            #pragma unroll
            for (int nh = 0; nh < 2; nh++) {
                int col = ng * 32 + nh * 16;
                uint32_t bd = s2u(Bs + (col + (lane & 7) + ((lane >> 4) & 1) * 8) * BSTH
                                     + kk + ((lane >> 3) & 1) * 8);
                uint32_t r0, r1, r2, r3;
                asm volatile(
                    "ldmatrix.sync.aligned.m8n8.x4.shared.b16 {%0,%1,%2,%3}, [%4];"
                    : "=r"(r0), "=r"(r1), "=r"(r2), "=r"(r3) : "r"(bd));
                bfr[nh * 2][0] = r0;  bfr[nh * 2][1] = r1;
                bfr[nh * 2 + 1][0] = r2; bfr[nh * 2 + 1][1] = r3;
            }
            #pragma unroll
            for (int nt = 0; nt < 4; nt++)
                #pragma unroll
                for (int mt = 0; mt < 4; mt++) {
                    asm volatile(
                        "mma.sync.aligned.m16n8k16.row.col.f32.f16.f16.f32 "
                        "{%0,%1,%2,%3}, {%4,%5,%6,%7}, {%8,%9}, {%0,%1,%2,%3};\n"
                        : "+f"(acc[mt][nt][0]), "+f"(acc[mt][nt][1]),
                          "+f"(acc[mt][nt][2]), "+f"(acc[mt][nt][3])
                        : "r"(a[mt][0]), "r"(a[mt][1]), "r"(a[mt][2]), "r"(a[mt][3]),
                          "r"(bfr[nt][0]), "r"(bfr[nt][1]));
                }
        }
        asm volatile("bar.sync %0, %1;" :: "r"(baridx), "n"(GSIZE) : "memory");
        if (j + 2 < NT_KG) issue_b(kofs + (j + 2) * BK, st);
    }

    // ---- Split-K reduction + softmax (block-wide) ----
    __syncthreads();
    float* Cs = (float*)sh;          // [64][242]

    if (kg == 1) {
        #pragma unroll
        for (int mt = 0; mt < 4; mt++)
            #pragma unroll
            for (int nt = 0; nt < 4; nt++) {
                int col = ng * 32 + nt * 8 + 2 * lk;
                if (col < N_DIM) {
                    int row = mt * 16 + lg;
                    Cs[row * CST + col    ]       = acc[mt][nt][0];
                    Cs[row * CST + col + 1]       = acc[mt][nt][1];
                    Cs[(row + 8) * CST + col    ] = acc[mt][nt][2];
                    Cs[(row + 8) * CST + col + 1] = acc[mt][nt][3];
                }
            }
    }
    __syncthreads();
    if (kg == 0) {
        #pragma unroll
        for (int mt = 0; mt < 4; mt++)
            #pragma unroll
            for (int nt = 0; nt < 4; nt++) {
                int col = ng * 32 + nt * 8 + 2 * lk;
                if (col < N_DIM) {
                    int row = mt * 16 + lg;
                    Cs[row * CST + col    ]       += acc[mt][nt][0];
                    Cs[row * CST + col + 1]       += acc[mt][nt][1];
                    Cs[(row + 8) * CST + col    ] += acc[mt][nt][2];
                    Cs[(row + 8) * CST + col + 1] += acc[mt][nt][3];
                }
            }
    }
    __syncthreads();

    // Softmax over K=15 per (row, head); write 16-tap-padded rows (stride 256)
    #pragma unroll
    for (int it = 0; it < 2; it++) {
        int task = it * NTHR + tid;
        int row = task >> 4, h = task & 15;
        const float* p = Cs + row * CST + h * K_TAPS;
        float mx = p[0];
        #pragma unroll
        for (int k = 1; k < K_TAPS; k++) mx = fmaxf(mx, p[k]);
        float e[16];
        float s = 0.f;
        #pragma unroll
        for (int k = 0; k < K_TAPS; k++) { e[k] = __expf(p[k] - mx); s += e[k]; }
        float r = 1.0f / s;
        #pragma unroll
        for (int k = 0; k < K_TAPS; k++) e[k] *= r;
        e[15] = 0.f;
        float4* o4 = (float4*)(g_w + (size_t)(m0 + row) * NPAD + h * 16);
        #pragma unroll
        for (int q = 0; q < 4; q++)
            o4[q] = make_float4(e[4 * q], e[4 * q + 1], e[4 * q + 2], e[4 * q + 3]);
    }
}

// ---------------- Dynamic depthwise conv (causal, K=15) ----------------
// out[t,b,c] = sum_k w[t,b,h(c),k] * x[t+k-14, b, c]
// Weights padded to 16 taps (LDS.128 x4); even/odd dual FMA chains.
#define TT 32   // time steps per block

extern "C" __global__ void __launch_bounds__(256, 2)
dynconv_kernel(const float* __restrict__ x, float* __restrict__ out) {
    __shared__ float ws[TT * NPAD];   // 32 KB

    const int tid = threadIdx.x;
    const int t0  = blockIdx.x * TT;
    const int b   = blockIdx.y;

    const int c4 = tid;           // float4 channel group (c = 4*tid)
    const int h  = tid >> 4;      // head

    const float4* x4 = (const float4*)x;
    float4*       o4 = (float4*)out;

    // Register window loads first: 15 independent LDGs in flight
    float4 win[K_TAPS];
    #pragma unroll
    for (int i = 0; i < K_TAPS; i++) {
        int t = t0 - 14 + i;
        win[i] = (t < 0) ? make_float4(0.f, 0.f, 0.f, 0.f)
                         : x4[(size_t)(t * B_DIM + b) * (C_DIM / 4) + c4];
    }

    // Weight tile: TT*256 floats = 2048 float4, 8 per thread
    const float4* gw4 = (const float4*)g_w;
    const size_t wbase = ((size_t)t0 * B_DIM + b) * (NPAD / 4);
    #pragma unroll
    for (int it = 0; it < 8; it++) {
        int idx = it * 256 + tid;            // 0..2047
        int tt = idx >> 6, q = idx & 63;
        ((float4*)ws)[tt * (NPAD / 4) + q] =
            gw4[wbase + (size_t)tt * B_DIM * (NPAD / 4) + q];
    }
    __syncthreads();

    #pragma unroll
    for (int tt = 0; tt < TT; tt++) {
        float4 nxt;
        if (tt + 1 < TT)
            nxt = x4[(size_t)((t0 + tt + 1) * B_DIM + b) * (C_DIM / 4) + c4];

        // 4x LDS.128 weight fetch (tap 15 is zero-padded, unused)
        const float4* w4 = (const float4*)(ws + tt * NPAD + h * 16);
        float4 wq0 = w4[0], wq1 = w4[1], wq2 = w4[2], wq3 = w4[3];
        float w[15] = { wq0.x, wq0.y, wq0.z, wq0.w,
                        wq1.x, wq1.y, wq1.z, wq1.w,
                        wq2.x, wq2.y, wq2.z, wq2.w,
                        wq3.x, wq3.y, wq3.z };

        // Dual accumulator chains (even/odd taps)
        float4 a0 = make_float4(0.f, 0.f, 0.f, 0.f);
        float4 a1 = make_float4(0.f, 0.f, 0.f, 0.f);
        #pragma unroll
        for (int k = 0; k < K_TAPS; k += 2) {
            const float4 xv = win[(tt + k) % K_TAPS];
            a0.x += w[k] * xv.x; a0.y += w[k] * xv.y;
            a0.z += w[k] * xv.z; a0.w += w[k] * xv.w;
        }
        #pragma unroll
        for (int k = 1; k < K_TAPS; k += 2) {
            const float4 xv = win[(tt + k) % K_TAPS];
            a1.x += w[k] * xv.x; a1.y += w[k] * xv.y;
            a1.z += w[k] * xv.z; a1.w += w[k] * xv.w;
        }
        float4 a = make_float4(a0.x + a1.x, a0.y + a1.y,
                               a0.z + a1.z, a0.w + a1.w);
        o4[(size_t)((t0 + tt) * B_DIM + b) * (C_DIM / 4) + c4] = a;
        if (tt + 1 < TT) win[tt % K_TAPS] = nxt;
    }
}

extern "C" void kernel_launch(void* const* d_in, const int* in_sizes, int n_in,
                              void* d_out, int out_size) {
    const float* x    = (const float*)d_in[0];   // (T, B, C) f32
    const float* Wlin = (const float*)d_in[1];   // (240, 1024) f32
    float* out = (float*)d_out;                  // (T, B, C) f32

    cudaFuncSetAttribute(gemm_softmax_kernel,
                         cudaFuncAttributeMaxDynamicSharedMemorySize,
                         GEMM_SMEM);

    cvt_b_kernel<<<60, 256>>>(Wlin);
    gemm_softmax_kernel<<<M_DIM / BM, NTHR, GEMM_SMEM>>>(x);
    dynconv_kernel<<<dim3(T_DIM / TT, B_DIM), 256>>>(x, out);
}

// round 9
// speedup vs baseline: 1.9719x; 1.1160x over previous
#include <cuda_runtime.h>
#include <cuda_fp16.h>
#include <cstdint>

// Problem constants
#define T_DIM 2048
#define B_DIM 4
#define C_DIM 1024
#define H_DIM 16
#define K_TAPS 15
#define M_DIM (T_DIM * B_DIM)     // 8192 rows (t*B + b)
#define N_DIM (H_DIM * K_TAPS)    // 240 logits per row
#define NPAD  256                 // padded: 16 taps per head
#define KD    C_DIM               // 1024 reduction dim

// Scratch: softmaxed dynamic weights (T*B, 256 padded) fp32; fp16 Wlin
__device__ float  g_w[M_DIM * NPAD];
__device__ __half g_wh[N_DIM * KD];

// ---------------- Prologue: Wlin -> fp16, once ----------------
extern "C" __global__ void __launch_bounds__(256)
cvt_b_kernel(const float* __restrict__ W) {
    int i = blockIdx.x * 256 + threadIdx.x;      // 61440 float4 total
    float4 v = ((const float4*)W)[i];
    __half2 h0 = __floats2half2_rn(v.x, v.y);
    __half2 h1 = __floats2half2_rn(v.z, v.w);
    uint2 o;
    o.x = *(uint32_t*)&h0;
    o.y = *(uint32_t*)&h1;
    ((uint2*)g_wh)[i] = o;
}

// ========== GEMM: barrier-free mainloop, fp16 mma + fused softmax =========
// Block: BM=64 rows, 256 threads = 8 warps. A (64x1024 fp16) fully resident
// in smem; each warp owns 32 N-cols and streams its own B with a private
// 3-stage cp.async ring (BK=32). No bar.sync in the mainloop.
#define NTHR   256
#define BM     64
#define BK     32
#define NTILE  (KD / BK)          // 32 k-tiles
#define ASTH   1032               // A row stride in halves (pad: conflict-free)
#define A_SMEM_H (BM * ASTH)      // 66048 halves = 132096 B
#define BSTH   40                 // B row stride in halves (80B)
#define BW_STG_H (32 * BSTH)      // per-warp stage: 1280 halves = 2560 B
#define B_SMEM_H (8 * 3 * BW_STG_H)   // 30720 halves = 61440 B
#define GEMM_SMEM ((A_SMEM_H + B_SMEM_H) * 2)  // 193536 B
#define CST    242

__device__ __forceinline__ uint32_t s2u(const void* p) {
    return (uint32_t)__cvta_generic_to_shared(p);
}

extern "C" __global__ void __launch_bounds__(NTHR, 1)
gemm_softmax_kernel(const float* __restrict__ x) {
    extern __shared__ __half sh[];
    const int tid  = threadIdx.x;
    const int wid  = tid >> 5;
    const int lane = tid & 31;
    const int m0   = blockIdx.x * BM;
    const int lg   = lane >> 2;
    const int lk   = lane & 3;

    __half* As = sh;
    __half* Bw = sh + A_SMEM_H + wid * 3 * BW_STG_H;   // this warp's B ring

    // Warp-private B tile issue: 32 cols x 32 k fp16 = 128 16B-chunks, 4/lane
    auto issue_b = [&](int kb, int st) {
        __half* Bs = Bw + st * BW_STG_H;
        #pragma unroll
        for (int i = 0; i < 4; i++) {
            int idx = i * 32 + lane;
            int nl = idx >> 2, kq = idx & 3;
            int n = wid * 32 + nl;
            int nn = (n < N_DIM) ? n : 0;
            unsigned bytes = (n < N_DIM) ? 16u : 0u;
            const __half* src = g_wh + (size_t)nn * KD + kb + kq * 8;
            uint32_t dst = s2u(Bs + nl * BSTH + kq * 8);
            asm volatile("cp.async.cg.shared.global [%0], [%1], 16, %2;\n"
                         :: "r"(dst), "l"(src), "r"(bytes));
        }
        asm volatile("cp.async.commit_group;\n");
    };

    // Prologue: start B ring (depth 2), then load full A (fp32 -> fp16 STS)
    issue_b(0, 0);
    issue_b(BK, 1);

    // A: 64 rows x 1024 = 16384 float4 chunks, 64 per thread
    #pragma unroll 8
    for (int i = 0; i < 64; i++) {
        int idx = i * NTHR + tid;
        int m = idx >> 8, cq = idx & 255;
        float4 v = *(const float4*)(x + (size_t)(m0 + m) * KD + cq * 4);
        __half2 h0 = __floats2half2_rn(v.x, v.y);
        __half2 h1 = __floats2half2_rn(v.z, v.w);
        uint2 o;
        o.x = *(uint32_t*)&h0;
        o.y = *(uint32_t*)&h1;
        *(uint2*)(As + (size_t)m * ASTH + cq * 4) = o;
    }
    __syncthreads();   // A visible to all warps; only sync before the loop

    float acc[4][4][4];   // [m-tile][n-tile][frag]
    #pragma unroll
    for (int a = 0; a < 4; a++)
        #pragma unroll
        for (int b = 0; b < 4; b++)
            #pragma unroll
            for (int c = 0; c < 4; c++) acc[a][b][c] = 0.f;

    for (int j = 0; j < NTILE; j++) {
        if (j == NTILE - 1) asm volatile("cp.async.wait_group 0;\n");
        else                asm volatile("cp.async.wait_group 1;\n");

        // Refill early: stage (j+2)%3 was consumed at iter j-1 (warp-private)
        if (j + 2 < NTILE) issue_b((j + 2) * BK, (j + 2) % 3);

        const __half* Bs = Bw + (j % 3) * BW_STG_H;
        const int kbase = j * BK;

        #pragma unroll
        for (int kk = 0; kk < BK; kk += 16) {
            uint32_t a[4][4];
            #pragma unroll
            for (int mt = 0; mt < 4; mt++) {
                uint32_t ad = s2u(As + (size_t)(mt * 16 + (lane & 15)) * ASTH
                                     + kbase + kk + (lane >> 4) * 8);
                asm volatile(
                    "ldmatrix.sync.aligned.m8n8.x4.shared.b16 {%0,%1,%2,%3}, [%4];"
                    : "=r"(a[mt][0]), "=r"(a[mt][1]), "=r"(a[mt][2]), "=r"(a[mt][3])
                    : "r"(ad));
            }
            uint32_t bfr[4][2];
            #pragma unroll
            for (int nh = 0; nh < 2; nh++) {
                int coll = nh * 16 + (lane & 7) + ((lane >> 4) & 1) * 8;
                uint32_t bd = s2u(Bs + coll * BSTH + kk + ((lane >> 3) & 1) * 8);
                uint32_t r0, r1, r2, r3;
                asm volatile(
                    "ldmatrix.sync.aligned.m8n8.x4.shared.b16 {%0,%1,%2,%3}, [%4];"
                    : "=r"(r0), "=r"(r1), "=r"(r2), "=r"(r3) : "r"(bd));
                bfr[nh * 2][0] = r0;  bfr[nh * 2][1] = r1;
                bfr[nh * 2 + 1][0] = r2; bfr[nh * 2 + 1][1] = r3;
            }
            #pragma unroll
            for (int nt = 0; nt < 4; nt++)
                #pragma unroll
                for (int mt = 0; mt < 4; mt++) {
                    asm volatile(
                        "mma.sync.aligned.m16n8k16.row.col.f32.f16.f16.f32 "
                        "{%0,%1,%2,%3}, {%4,%5,%6,%7}, {%8,%9}, {%0,%1,%2,%3};\n"
                        : "+f"(acc[mt][nt][0]), "+f"(acc[mt][nt][1]),
                          "+f"(acc[mt][nt][2]), "+f"(acc[mt][nt][3])
                        : "r"(a[mt][0]), "r"(a[mt][1]), "r"(a[mt][2]), "r"(a[mt][3]),
                          "r"(bfr[nt][0]), "r"(bfr[nt][1]));
                }
        }
    }

    // ---- Epilogue: stage C in smem (full-K per warp, no reduction) ----
    __syncthreads();                 // all warps done with A/B smem
    float* Cs = (float*)sh;          // [64][242]

    #pragma unroll
    for (int mt = 0; mt < 4; mt++)
        #pragma unroll
        for (int nt = 0; nt < 4; nt++) {
            int col = wid * 32 + nt * 8 + 2 * lk;
            if (col < N_DIM) {
                int row = mt * 16 + lg;
                Cs[row * CST + col    ]       = acc[mt][nt][0];
                Cs[row * CST + col + 1]       = acc[mt][nt][1];
                Cs[(row + 8) * CST + col    ] = acc[mt][nt][2];
                Cs[(row + 8) * CST + col + 1] = acc[mt][nt][3];
            }
        }
    __syncthreads();

    // Softmax over K=15 per (row, head); write 16-tap-padded rows (stride 256)
    #pragma unroll
    for (int it = 0; it < 4; it++) {
        int task = it * NTHR + tid;          // 64 rows x 16 heads
        int row = task >> 4, h = task & 15;
        const float* p = Cs + row * CST + h * K_TAPS;
        float mx = p[0];
        #pragma unroll
        for (int k = 1; k < K_TAPS; k++) mx = fmaxf(mx, p[k]);
        float e[16];
        float s = 0.f;
        #pragma unroll
        for (int k = 0; k < K_TAPS; k++) { e[k] = __expf(p[k] - mx); s += e[k]; }
        float r = 1.0f / s;
        #pragma unroll
        for (int k = 0; k < K_TAPS; k++) e[k] *= r;
        e[15] = 0.f;
        float4* o4 = (float4*)(g_w + (size_t)(m0 + row) * NPAD + h * 16);
        #pragma unroll
        for (int q = 0; q < 4; q++)
            o4[q] = make_float4(e[4 * q], e[4 * q + 1], e[4 * q + 2], e[4 * q + 3]);
    }
}

// ---------------- Dynamic depthwise conv (causal, K=15) ----------------
// out[t,b,c] = sum_k w[t,b,h(c),k] * x[t+k-14, b, c]
// Weights padded to 16 taps (LDS.128 x4); even/odd dual FMA chains.
#define TT 32   // time steps per block

extern "C" __global__ void __launch_bounds__(256, 2)
dynconv_kernel(const float* __restrict__ x, float* __restrict__ out) {
    __shared__ float ws[TT * NPAD];   // 32 KB

    const int tid = threadIdx.x;
    const int t0  = blockIdx.x * TT;
    const int b   = blockIdx.y;

    const int c4 = tid;           // float4 channel group (c = 4*tid)
    const int h  = tid >> 4;      // head

    const float4* x4 = (const float4*)x;
    float4*       o4 = (float4*)out;

    // Register window loads first: 15 independent LDGs in flight
    float4 win[K_TAPS];
    #pragma unroll
    for (int i = 0; i < K_TAPS; i++) {
        int t = t0 - 14 + i;
        win[i] = (t < 0) ? make_float4(0.f, 0.f, 0.f, 0.f)
                         : x4[(size_t)(t * B_DIM + b) * (C_DIM / 4) + c4];
    }

    // Weight tile: TT*256 floats = 2048 float4, 8 per thread
    const float4* gw4 = (const float4*)g_w;
    const size_t wbase = ((size_t)t0 * B_DIM + b) * (NPAD / 4);
    #pragma unroll
    for (int it = 0; it < 8; it++) {
        int idx = it * 256 + tid;            // 0..2047
        int tt = idx >> 6, q = idx & 63;
        ((float4*)ws)[tt * (NPAD / 4) + q] =
            gw4[wbase + (size_t)tt * B_DIM * (NPAD / 4) + q];
    }
    __syncthreads();

    #pragma unroll
    for (int tt = 0; tt < TT; tt++) {
        float4 nxt;
        if (tt + 1 < TT)
            nxt = x4[(size_t)((t0 + tt + 1) * B_DIM + b) * (C_DIM / 4) + c4];

        // 4x LDS.128 weight fetch (tap 15 is zero-padded, unused)
        const float4* w4 = (const float4*)(ws + tt * NPAD + h * 16);
        float4 wq0 = w4[0], wq1 = w4[1], wq2 = w4[2], wq3 = w4[3];
        float w[15] = { wq0.x, wq0.y, wq0.z, wq0.w,
                        wq1.x, wq1.y, wq1.z, wq1.w,
                        wq2.x, wq2.y, wq2.z, wq2.w,
                        wq3.x, wq3.y, wq3.z };

        // Dual accumulator chains (even/odd taps)
        float4 a0 = make_float4(0.f, 0.f, 0.f, 0.f);
        float4 a1 = make_float4(0.f, 0.f, 0.f, 0.f);
        #pragma unroll
        for (int k = 0; k < K_TAPS; k += 2) {
            const float4 xv = win[(tt + k) % K_TAPS];
            a0.x += w[k] * xv.x; a0.y += w[k] * xv.y;
            a0.z += w[k] * xv.z; a0.w += w[k] * xv.w;
        }
        #pragma unroll
        for (int k = 1; k < K_TAPS; k += 2) {
            const float4 xv = win[(tt + k) % K_TAPS];
            a1.x += w[k] * xv.x; a1.y += w[k] * xv.y;
            a1.z += w[k] * xv.z; a1.w += w[k] * xv.w;
        }
        float4 a = make_float4(a0.x + a1.x, a0.y + a1.y,
                               a0.z + a1.z, a0.w + a1.w);
        o4[(size_t)((t0 + tt) * B_DIM + b) * (C_DIM / 4) + c4] = a;
        if (tt + 1 < TT) win[tt % K_TAPS] = nxt;
    }
}

extern "C" void kernel_launch(void* const* d_in, const int* in_sizes, int n_in,
                              void* d_out, int out_size) {
    const float* x    = (const float*)d_in[0];   // (T, B, C) f32
    const float* Wlin = (const float*)d_in[1];   // (240, 1024) f32
    float* out = (float*)d_out;                  // (T, B, C) f32

    cudaFuncSetAttribute(gemm_softmax_kernel,
                         cudaFuncAttributeMaxDynamicSharedMemorySize,
                         GEMM_SMEM);

    cvt_b_kernel<<<240, 256>>>(Wlin);
    gemm_softmax_kernel<<<M_DIM / BM, NTHR, GEMM_SMEM>>>(x);
    dynconv_kernel<<<dim3(T_DIM / TT, B_DIM), 256>>>(x, out);
}